// round 16
// baseline (speedup 1.0000x reference)
#include <cuda_runtime.h>
#include <cuda.h>
#include <cuda_fp16.h>
#include <cstdint>

#define NE 8
#define DMODEL 1024
#define DFF 4096
#define TTOK 2048
#define NSPLIT 4

// ---------------- scratch ----------------
__device__ int g_perm[TTOK];
__device__ int g_off[NE + 1];
__device__ __align__(1024) __half g_x16[(size_t)TTOK * DMODEL];
__device__ __align__(1024) __half g_h[(size_t)TTOK * DFF];
__device__ __align__(16) float g_part[NSPLIT][TTOK][DMODEL];

// ---------------- helpers ----------------
__device__ __forceinline__ uint32_t s2u(const void* p) {
    return (uint32_t)__cvta_generic_to_shared(p);
}
__device__ __forceinline__ void mbar_init(uint32_t a, uint32_t c) {
    asm volatile("mbarrier.init.shared.b64 [%0], %1;" :: "r"(a), "r"(c) : "memory");
}
__device__ __forceinline__ void mbar_expect(uint32_t a, uint32_t b) {
    asm volatile("mbarrier.arrive.expect_tx.shared.b64 _, [%0], %1;" :: "r"(a), "r"(b) : "memory");
}
__device__ __forceinline__ void mbar_wait(uint32_t a, uint32_t ph) {
    asm volatile("{\n\t.reg .pred P;\n\tWL_%=:\n\t"
        "mbarrier.try_wait.parity.acquire.cta.shared::cta.b64 P, [%0], %1, 0x989680;\n\t"
        "@P bra.uni WD_%=;\n\tbra.uni WL_%=;\n\tWD_%=:\n\t}" :: "r"(a), "r"(ph) : "memory");
}
__device__ __forceinline__ void tma2d(uint32_t d, const CUtensorMap* m, int cx, int cy, uint32_t b) {
    asm volatile("cp.async.bulk.tensor.2d.shared::cta.global.tile.mbarrier::complete_tx::bytes "
        "[%0], [%1, {%2, %3}], [%4];" :: "r"(d), "l"(m), "r"(cx), "r"(cy), "r"(b) : "memory");
}
__device__ __forceinline__ void tma3d(uint32_t d, const CUtensorMap* m, int cx, int cy, int cz, uint32_t b) {
    asm volatile("cp.async.bulk.tensor.3d.shared::cta.global.tile.mbarrier::complete_tx::bytes "
        "[%0], [%1, {%2, %3, %4}], [%5];" :: "r"(d), "l"(m), "r"(cx), "r"(cy), "r"(cz), "r"(b) : "memory");
}
__device__ __forceinline__ void ldsm4(uint32_t* r, uint32_t a) {
    asm volatile("ldmatrix.sync.aligned.m8n8.x4.shared.b16 {%0,%1,%2,%3}, [%4];"
                 : "=r"(r[0]), "=r"(r[1]), "=r"(r[2]), "=r"(r[3]) : "r"(a));
}
__device__ __forceinline__ void ldsm4t(uint32_t* r, uint32_t a) {
    asm volatile("ldmatrix.sync.aligned.m8n8.x4.trans.shared.b16 {%0,%1,%2,%3}, [%4];"
                 : "=r"(r[0]), "=r"(r[1]), "=r"(r[2]), "=r"(r[3]) : "r"(a));
}
__device__ __forceinline__ void mma16(float* c, const uint32_t* a, uint32_t b0, uint32_t b1) {
    asm volatile("mma.sync.aligned.m16n8k16.row.col.f32.f16.f16.f32 "
                 "{%0,%1,%2,%3},{%4,%5,%6,%7},{%8,%9},{%0,%1,%2,%3};"
                 : "+f"(c[0]), "+f"(c[1]), "+f"(c[2]), "+f"(c[3])
                 : "r"(a[0]), "r"(a[1]), "r"(a[2]), "r"(a[3]), "r"(b0), "r"(b1));
}
// read two adjacent swizzled float4 from staging, pack to 8 halfs, one STS.128
__device__ __forceinline__ void cvt2_sts128(const char* smem0, uint32_t src_base,
                                            uint32_t swz_arg, char* dst) {
    float4 v0 = *(const float4*)(smem0 + src_base + (((swz_arg)      ^ (((swz_arg)      >> 3) & 0x70))));
    uint32_t a2 = swz_arg + 16;
    float4 v1 = *(const float4*)(smem0 + src_base + ((a2 ^ ((a2 >> 3) & 0x70))));
    __half2 h0 = __floats2half2_rn(v0.x, v0.y);
    __half2 h1 = __floats2half2_rn(v0.z, v0.w);
    __half2 h2 = __floats2half2_rn(v1.x, v1.y);
    __half2 h3 = __floats2half2_rn(v1.z, v1.w);
    uint4 o = make_uint4(*(uint32_t*)&h0, *(uint32_t*)&h1, *(uint32_t*)&h2, *(uint32_t*)&h3);
    *(uint4*)dst = o;
}
#define SWZ128(off) ((off) ^ (((off) >> 3) & 0x70))

// ---------------- kernel 1: bucket tokens by expert ----------------
__global__ void moe_build_perm(const void* eidx_raw) {
    __shared__ int cnt[NE], base[NE], nz;
    int t = threadIdx.x;
    if (t < NE) cnt[t] = 0;
    if (t == 0) nz = 0;
    __syncthreads();
    const int* i32 = (const int*)eidx_raw;
    for (int i = t; i < TTOK / 2; i += blockDim.x)
        if (i32[2 * i + 1] != 0) atomicOr(&nz, 1);
    __syncthreads();
    bool is64 = (nz == 0);
    const long long* i64 = (const long long*)eidx_raw;
    for (int i = t; i < TTOK; i += blockDim.x)
        atomicAdd(&cnt[is64 ? (int)i64[i] : i32[i]], 1);
    __syncthreads();
    if (t == 0) {
        int s = 0;
        for (int e = 0; e < NE; e++) { g_off[e] = s; base[e] = s; s += cnt[e]; }
        g_off[NE] = s;
    }
    __syncthreads();
    for (int i = t; i < TTOK; i += blockDim.x) {
        int e = is64 ? (int)i64[i] : i32[i];
        g_perm[atomicAdd(&base[e], 1)] = i;
    }
}

// ---------------- kernel 2: gather + fp16 convert ----------------
__global__ void moe_gather(const float* __restrict__ x) {
    int src = g_perm[blockIdx.x];
    float4 v = ((const float4*)(x + (size_t)src * DMODEL))[threadIdx.x];
    __half2* d = (__half2*)(g_x16 + (size_t)blockIdx.x * DMODEL + threadIdx.x * 4);
    d[0] = __floats2half2_rn(v.x, v.y);
    d[1] = __floats2half2_rn(v.z, v.w);
}

// gemm1: A 2x16384 @0; STG(fp32 g+u) 32768 @32768; B16 g 2x9216 @65536, u 2x9216 @83968; mbar @102400
#define G1_A    0
#define G1_STG  32768
#define G1_B16G 65536
#define G1_B16U 83968
#define G1_MBAR 102400
#define G1_SMEM 102528
// gemm2: A 3x16384 @0; STG 2x16384 @49152; B16 2x9216 @81920; mbar @100352
#define G2_A    0
#define G2_STG  49152
#define G2_B16  81920
#define G2_MBAR 100352
#define G2_SMEM 100480

// ---------------- kernel 3: gate+up GEMM + SwiGLU ----------------
__global__ void __launch_bounds__(256, 2)
moe_gateup(const __grid_constant__ CUtensorMap tmA,
           const __grid_constant__ CUtensorMap tmG,
           const __grid_constant__ CUtensorMap tmU) {
    extern __shared__ char smem[];
    const int e = blockIdx.z, seg = g_off[e], cnt = g_off[e + 1] - seg;
    const int mtile = blockIdx.y;
    if (mtile * 128 >= cnt) return;
    const int m0g = seg + mtile * 128, n0 = blockIdx.x * 64;

    const int tid = threadIdx.x, warp = tid >> 5, lane = tid & 31;
    const int wm = warp >> 1, wn = warp & 1;
    const uint32_t sb = s2u(smem);

    if (tid == 0) {
        mbar_init(sb + G1_MBAR + 0, 1);
        mbar_init(sb + G1_MBAR + 8, 1);
        mbar_init(sb + G1_MBAR + 16, 1);
    }
    __syncthreads();

    auto issueA = [&](int s) {
        uint32_t mb = sb + G1_MBAR + 8 * (s & 1);
        mbar_expect(mb, 16384);
        tma2d(sb + G1_A + (s & 1) * 16384, &tmA, s * 64, m0g, mb);
    };
    auto issueB = [&](int s) {
        uint32_t mb = sb + G1_MBAR + 16;
        mbar_expect(mb, 32768);
        int k0 = s * 64;
        #pragma unroll
        for (int sub = 0; sub < 2; sub++) {
            tma3d(sb + G1_STG + sub * 8192,          &tmG, n0 + sub * 32, k0, e, mb);
            tma3d(sb + G1_STG + 16384 + sub * 8192,  &tmU, n0 + sub * 32, k0, e, mb);
        }
    };

    if (tid == 0) { issueA(0); issueB(0); }

    float cg[2][4][4] = {}, cu[2][4][4] = {};
    const int KT = DMODEL / 64;
    for (int s = 0; s < KT; s++) {
        const int b1 = s & 1;
        mbar_wait(sb + G1_MBAR + 16, s & 1);
        // convert: 1024 uint4 total (2 matrices x 512), 4 per thread
        #pragma unroll
        for (int i = 0; i < 4; i++) {
            int id = tid + i * 256;
            int m = id >> 9, id2 = id & 511;
            int r = id2 >> 3, c8 = id2 & 7, sub = c8 >> 2;
            uint32_t swz_arg = (uint32_t)(r * 128 + (c8 & 3) * 32);
            char* dst = smem + (m ? G1_B16U : G1_B16G) + b1 * 9216 + r * 144 + c8 * 16;
            cvt2_sts128(smem, G1_STG + m * 16384 + sub * 8192, swz_arg, dst);
        }
        mbar_wait(sb + G1_MBAR + 8 * b1, (s >> 1) & 1);
        __syncthreads();
        if (s + 1 < KT && tid == 0) { issueB(s + 1); issueA(s + 1); }
        uint32_t sA = sb + G1_A + b1 * 16384;
        uint32_t sG = sb + G1_B16G + b1 * 9216;
        uint32_t sU = sb + G1_B16U + b1 * 9216;
        #pragma unroll
        for (int ks = 0; ks < 4; ks++) {
            uint32_t a[2][4], bg[8], bu[8];
            #pragma unroll
            for (int mt = 0; mt < 2; mt++) {
                int row = wm * 32 + mt * 16 + (lane & 15);
                uint32_t off = row * 128 + ks * 32 + (lane >> 4) * 16;
                ldsm4(a[mt], sA + SWZ128(off));
            }
            #pragma unroll
            for (int h = 0; h < 2; h++) {
                int kr = ks * 16 + (lane & 15);
                int nc = wn * 32 + h * 16 + (lane >> 4) * 8;
                ldsm4t(&bg[h * 4], sG + kr * 144 + nc * 2);
                ldsm4t(&bu[h * 4], sU + kr * 144 + nc * 2);
            }
            #pragma unroll
            for (int mt = 0; mt < 2; mt++)
                #pragma unroll
                for (int nt = 0; nt < 4; nt++) {
                    mma16(cg[mt][nt], a[mt], bg[nt * 2], bg[nt * 2 + 1]);
                    mma16(cu[mt][nt], a[mt], bu[nt * 2], bu[nt * 2 + 1]);
                }
        }
    }

    const int quad = lane >> 2, tq = lane & 3;
    const int rowsb = cnt - mtile * 128;
    #pragma unroll
    for (int mt = 0; mt < 2; mt++)
        #pragma unroll
        for (int nt = 0; nt < 4; nt++)
            #pragma unroll
            for (int hr = 0; hr < 2; hr++) {
                int row = wm * 32 + mt * 16 + quad + hr * 8;
                if (row < rowsb) {
                    int c = wn * 32 + nt * 8 + tq * 2;
                    float ga = cg[mt][nt][hr * 2], gb = cg[mt][nt][hr * 2 + 1];
                    float ua = cu[mt][nt][hr * 2], ub = cu[mt][nt][hr * 2 + 1];
                    float ha = ua * (ga / (1.f + __expf(-ga)));
                    float hb = ub * (gb / (1.f + __expf(-gb)));
                    *(__half2*)(g_h + (size_t)(m0g + row) * DFF + n0 + c) =
                        __floats2half2_rn(ha, hb);
                }
            }
}

// ---------------- kernel 4: down GEMM split-K (R14 structure, STS.128 convert) ----------------
__global__ void __launch_bounds__(256, 2)
moe_down_part(const __grid_constant__ CUtensorMap tmA,
              const __grid_constant__ CUtensorMap tmD) {
    extern __shared__ char smem[];
    const int split = blockIdx.z & (NSPLIT - 1), e = blockIdx.z / NSPLIT;
    const int seg = g_off[e], cnt = g_off[e + 1] - seg;
    const int mtile = blockIdx.y;
    if (mtile * 128 >= cnt) return;
    const int m0g = seg + mtile * 128, n0 = blockIdx.x * 64;
    const int kbase = split * (DFF / NSPLIT);

    const int tid = threadIdx.x, warp = tid >> 5, lane = tid & 31;
    const int wm = warp >> 1, wn = warp & 1;
    const uint32_t sb = s2u(smem);

    if (tid == 0) {
        for (int i = 0; i < 3; i++) mbar_init(sb + G2_MBAR + 8 * i, 1);
        mbar_init(sb + G2_MBAR + 24, 1);
        mbar_init(sb + G2_MBAR + 32, 1);
    }
    __syncthreads();

    auto issueA = [&](int s) {
        uint32_t mb = sb + G2_MBAR + 8 * (s % 3);
        mbar_expect(mb, 16384);
        tma2d(sb + G2_A + (s % 3) * 16384, &tmA, kbase + s * 64, m0g, mb);
    };
    auto issueB = [&](int s) {
        uint32_t mb = sb + G2_MBAR + 24 + 8 * (s & 1);
        mbar_expect(mb, 16384);
        int k0 = kbase + s * 64;
        #pragma unroll
        for (int sub = 0; sub < 2; sub++)
            tma3d(sb + G2_STG + (s & 1) * 16384 + sub * 8192, &tmD,
                  n0 + sub * 32, k0, e, mb);
    };

    if (tid == 0) { issueA(0); issueA(1); issueB(0); issueB(1); }

    float acc[2][4][4] = {};
    const int KT = (DFF / NSPLIT) / 64;            // 16 stages
    for (int s = 0; s < KT; s++) {
        const int b1 = s & 1, slotA = s % 3;
        mbar_wait(sb + G2_MBAR + 24 + 8 * b1, (s >> 1) & 1);
        // convert: 512 uint4, 2 per thread
        #pragma unroll
        for (int i = 0; i < 2; i++) {
            int id = tid + i * 256;
            int r = id >> 3, c8 = id & 7, sub = c8 >> 2;
            uint32_t swz_arg = (uint32_t)(r * 128 + (c8 & 3) * 32);
            char* dst = smem + G2_B16 + b1 * 9216 + r * 144 + c8 * 16;
            cvt2_sts128(smem, G2_STG + b1 * 16384 + sub * 8192, swz_arg, dst);
        }
        mbar_wait(sb + G2_MBAR + 8 * slotA, (s / 3) & 1);
        __syncthreads();
        if (s + 2 < KT && tid == 0) { issueB(s + 2); issueA(s + 2); }
        uint32_t sA = sb + G2_A + slotA * 16384;
        uint32_t sB = sb + G2_B16 + b1 * 9216;
        #pragma unroll
        for (int ks = 0; ks < 4; ks++) {
            uint32_t a[2][4], bb[8];
            #pragma unroll
            for (int mt = 0; mt < 2; mt++) {
                int row = wm * 32 + mt * 16 + (lane & 15);
                uint32_t off = row * 128 + ks * 32 + (lane >> 4) * 16;
                ldsm4(a[mt], sA + SWZ128(off));
            }
            #pragma unroll
            for (int h = 0; h < 2; h++) {
                int kr = ks * 16 + (lane & 15);
                int nc = wn * 32 + h * 16 + (lane >> 4) * 8;
                ldsm4t(&bb[h * 4], sB + kr * 144 + nc * 2);
            }
            #pragma unroll
            for (int mt = 0; mt < 2; mt++)
                #pragma unroll
                for (int nt = 0; nt < 4; nt++)
                    mma16(acc[mt][nt], a[mt], bb[nt * 2], bb[nt * 2 + 1]);
        }
    }

    const int quad = lane >> 2, tq = lane & 3;
    const int rowsb = cnt - mtile * 128;
    #pragma unroll
    for (int mt = 0; mt < 2; mt++)
        #pragma unroll
        for (int nt = 0; nt < 4; nt++)
            #pragma unroll
            for (int hr = 0; hr < 2; hr++) {
                int row = wm * 32 + mt * 16 + quad + hr * 8;
                if (row < rowsb) {
                    int c = wn * 32 + nt * 8 + tq * 2;
                    float2 v = make_float2(acc[mt][nt][hr * 2], acc[mt][nt][hr * 2 + 1]);
                    *(float2*)(&g_part[split][m0g + row][n0 + c]) = v;
                }
            }
}

// ---------------- kernel 5: reduce partials + scatter ----------------
__global__ void moe_reduce(float* __restrict__ out) {
    int t = blockIdx.x, d = threadIdx.x * 4;
    float4 a = *(const float4*)(&g_part[0][t][d]);
    float4 b = *(const float4*)(&g_part[1][t][d]);
    float4 c = *(const float4*)(&g_part[2][t][d]);
    float4 e = *(const float4*)(&g_part[3][t][d]);
    float4 r;
    r.x = (a.x + b.x) + (c.x + e.x);
    r.y = (a.y + b.y) + (c.y + e.y);
    r.z = (a.z + b.z) + (c.z + e.z);
    r.w = (a.w + b.w) + (c.w + e.w);
    *(float4*)(out + (size_t)g_perm[t] * DMODEL + d) = r;
}

// ---------------- host ----------------
typedef CUresult (*EncFn)(CUtensorMap*, CUtensorMapDataType, cuuint32_t, void*,
    const cuuint64_t*, const cuuint64_t*, const cuuint32_t*, const cuuint32_t*,
    CUtensorMapInterleave, CUtensorMapSwizzle, CUtensorMapL2promotion, CUtensorMapFloatOOBfill);

static void enc_half2d(EncFn f, CUtensorMap* m, void* p, uint64_t d0, uint64_t d1) {
    cuuint64_t dims[2] = {d0, d1}, str[1] = {d0 * 2ULL};
    cuuint32_t box[2] = {64, 128}, es[2] = {1, 1};
    f(m, CU_TENSOR_MAP_DATA_TYPE_UINT16, 2, p, dims, str, box, es,
      CU_TENSOR_MAP_INTERLEAVE_NONE, CU_TENSOR_MAP_SWIZZLE_128B,
      CU_TENSOR_MAP_L2_PROMOTION_L2_128B, CU_TENSOR_MAP_FLOAT_OOB_FILL_NONE);
}
static void enc_w32(EncFn f, CUtensorMap* m, void* p, uint64_t n_dim, uint64_t k_dim) {
    cuuint64_t dims[3] = {n_dim, k_dim, NE};
    cuuint64_t str[2] = {n_dim * 4ULL, n_dim * k_dim * 4ULL};
    cuuint32_t box[3] = {32, 64, 1}, es[3] = {1, 1, 1};
    f(m, CU_TENSOR_MAP_DATA_TYPE_FLOAT32, 3, p, dims, str, box, es,
      CU_TENSOR_MAP_INTERLEAVE_NONE, CU_TENSOR_MAP_SWIZZLE_128B,
      CU_TENSOR_MAP_L2_PROMOTION_L2_128B, CU_TENSOR_MAP_FLOAT_OOB_FILL_NONE);
}

extern "C" void kernel_launch(void* const* d_in, const int* in_sizes, int n_in,
                              void* d_out, int out_size) {
    const float* x  = (const float*)d_in[0];
    const void*  ei = d_in[1];
    void* wg = (void*)d_in[2];
    void* wu = (void*)d_in[3];
    void* wd = (void*)d_in[4];
    float* out = (float*)d_out;

    EncFn enc = nullptr;
    cudaDriverEntryPointQueryResult qr;
    cudaGetDriverEntryPoint("cuTensorMapEncodeTiled", (void**)&enc, cudaEnableDefault, &qr);

    void *p_x16 = nullptr, *p_h = nullptr;
    cudaGetSymbolAddress(&p_x16, g_x16);
    cudaGetSymbolAddress(&p_h, g_h);

    CUtensorMap mA1, mA2, mG, mU, mD;
    enc_half2d(enc, &mA1, p_x16, DMODEL, TTOK);
    enc_half2d(enc, &mA2, p_h, DFF, TTOK);
    enc_w32(enc, &mG, wg, DFF, DMODEL);
    enc_w32(enc, &mU, wu, DFF, DMODEL);
    enc_w32(enc, &mD, wd, DMODEL, DFF);

    cudaFuncSetAttribute(moe_gateup, cudaFuncAttributeMaxDynamicSharedMemorySize, G1_SMEM);
    cudaFuncSetAttribute(moe_down_part, cudaFuncAttributeMaxDynamicSharedMemorySize, G2_SMEM);

    moe_build_perm<<<1, 1024>>>(ei);
    moe_gather<<<TTOK, 256>>>(x);
    moe_gateup<<<dim3(DFF / 64, TTOK / 128, NE), 256, G1_SMEM>>>(mA1, mG, mU);
    moe_down_part<<<dim3(DMODEL / 64, TTOK / 128, NE * NSPLIT), 256, G2_SMEM>>>(mA2, mD);
    moe_reduce<<<TTOK, 256>>>(out);
}

// round 17
// speedup vs baseline: 1.0505x; 1.0505x over previous
#include <cuda_runtime.h>
#include <cuda.h>
#include <cuda_fp16.h>
#include <cstdint>

#define NE 8
#define DMODEL 1024
#define DFF 4096
#define TTOK 2048
#define NSPLIT 4

// ---------------- scratch ----------------
__device__ int g_perm[TTOK];
__device__ int g_off[NE + 1];
__device__ __align__(1024) __half g_x16[(size_t)TTOK * DMODEL];
__device__ __align__(1024) __half g_h[(size_t)TTOK * DFF];
__device__ __align__(16) float g_part[NSPLIT][TTOK][DMODEL];

// ---------------- helpers ----------------
__device__ __forceinline__ uint32_t s2u(const void* p) {
    return (uint32_t)__cvta_generic_to_shared(p);
}
__device__ __forceinline__ void mbar_init(uint32_t a, uint32_t c) {
    asm volatile("mbarrier.init.shared.b64 [%0], %1;" :: "r"(a), "r"(c) : "memory");
}
__device__ __forceinline__ void mbar_expect(uint32_t a, uint32_t b) {
    asm volatile("mbarrier.arrive.expect_tx.shared.b64 _, [%0], %1;" :: "r"(a), "r"(b) : "memory");
}
__device__ __forceinline__ void mbar_wait(uint32_t a, uint32_t ph) {
    asm volatile("{\n\t.reg .pred P;\n\tWL_%=:\n\t"
        "mbarrier.try_wait.parity.acquire.cta.shared::cta.b64 P, [%0], %1, 0x989680;\n\t"
        "@P bra.uni WD_%=;\n\tbra.uni WL_%=;\n\tWD_%=:\n\t}" :: "r"(a), "r"(ph) : "memory");
}
__device__ __forceinline__ void tma2d(uint32_t d, const CUtensorMap* m, int cx, int cy, uint32_t b) {
    asm volatile("cp.async.bulk.tensor.2d.shared::cta.global.tile.mbarrier::complete_tx::bytes "
        "[%0], [%1, {%2, %3}], [%4];" :: "r"(d), "l"(m), "r"(cx), "r"(cy), "r"(b) : "memory");
}
__device__ __forceinline__ void tma3d(uint32_t d, const CUtensorMap* m, int cx, int cy, int cz, uint32_t b) {
    asm volatile("cp.async.bulk.tensor.3d.shared::cta.global.tile.mbarrier::complete_tx::bytes "
        "[%0], [%1, {%2, %3, %4}], [%5];" :: "r"(d), "l"(m), "r"(cx), "r"(cy), "r"(cz), "r"(b) : "memory");
}
__device__ __forceinline__ void ldsm4(uint32_t* r, uint32_t a) {
    asm volatile("ldmatrix.sync.aligned.m8n8.x4.shared.b16 {%0,%1,%2,%3}, [%4];"
                 : "=r"(r[0]), "=r"(r[1]), "=r"(r[2]), "=r"(r[3]) : "r"(a));
}
__device__ __forceinline__ void ldsm4t(uint32_t* r, uint32_t a) {
    asm volatile("ldmatrix.sync.aligned.m8n8.x4.trans.shared.b16 {%0,%1,%2,%3}, [%4];"
                 : "=r"(r[0]), "=r"(r[1]), "=r"(r[2]), "=r"(r[3]) : "r"(a));
}
__device__ __forceinline__ void mma16(float* c, const uint32_t* a, uint32_t b0, uint32_t b1) {
    asm volatile("mma.sync.aligned.m16n8k16.row.col.f32.f16.f16.f32 "
                 "{%0,%1,%2,%3},{%4,%5,%6,%7},{%8,%9},{%0,%1,%2,%3};"
                 : "+f"(c[0]), "+f"(c[1]), "+f"(c[2]), "+f"(c[3])
                 : "r"(a[0]), "r"(a[1]), "r"(a[2]), "r"(a[3]), "r"(b0), "r"(b1));
}
__device__ __forceinline__ void sts_f4h(char* base, int id, float4 v) {
    int r = id >> 4, c = id & 15;
    __half2* d = (__half2*)(base + r * 144 + c * 8);
    d[0] = __floats2half2_rn(v.x, v.y);
    d[1] = __floats2half2_rn(v.z, v.w);
}
#define SWZ128(off) ((off) ^ (((off) >> 3) & 0x70))

// ---------------- kernel 1: bucket tokens by expert ----------------
__global__ void moe_build_perm(const void* eidx_raw) {
    __shared__ int cnt[NE], base[NE], nz;
    int t = threadIdx.x;
    if (t < NE) cnt[t] = 0;
    if (t == 0) nz = 0;
    __syncthreads();
    const int* i32 = (const int*)eidx_raw;
    for (int i = t; i < TTOK / 2; i += blockDim.x)
        if (i32[2 * i + 1] != 0) atomicOr(&nz, 1);
    __syncthreads();
    bool is64 = (nz == 0);
    const long long* i64 = (const long long*)eidx_raw;
    for (int i = t; i < TTOK; i += blockDim.x)
        atomicAdd(&cnt[is64 ? (int)i64[i] : i32[i]], 1);
    __syncthreads();
    if (t == 0) {
        int s = 0;
        for (int e = 0; e < NE; e++) { g_off[e] = s; base[e] = s; s += cnt[e]; }
        g_off[NE] = s;
    }
    __syncthreads();
    for (int i = t; i < TTOK; i += blockDim.x) {
        int e = is64 ? (int)i64[i] : i32[i];
        g_perm[atomicAdd(&base[e], 1)] = i;
    }
}

// ---------------- kernel 2: gather + fp16 convert ----------------
__global__ void moe_gather(const float* __restrict__ x) {
    int src = g_perm[blockIdx.x];
    float4 v = ((const float4*)(x + (size_t)src * DMODEL))[threadIdx.x];
    __half2* d = (__half2*)(g_x16 + (size_t)blockIdx.x * DMODEL + threadIdx.x * 4);
    d[0] = __floats2half2_rn(v.x, v.y);
    d[1] = __floats2half2_rn(v.z, v.w);
}

// gemm1: A 2x16384 @0; STG(fp32 g+u) 32768 @32768; B16 g 2x9216 @65536, u 2x9216 @83968; mbar @102400
#define G1_A    0
#define G1_STG  32768
#define G1_B16G 65536
#define G1_B16U 83968
#define G1_MBAR 102400
#define G1_SMEM 102528
// gemm2: A 3x16384 @0; STG 2x16384 @49152; B16 2x9216 @81920; mbar @100352
#define G2_A    0
#define G2_STG  49152
#define G2_B16  81920
#define G2_MBAR 100352
#define G2_SMEM 100480

// ---------------- kernel 3: gate+up GEMM + SwiGLU (R14 + A-before-B issue) ----------------
__global__ void __launch_bounds__(256, 2)
moe_gateup(const __grid_constant__ CUtensorMap tmA,
           const __grid_constant__ CUtensorMap tmG,
           const __grid_constant__ CUtensorMap tmU) {
    extern __shared__ char smem[];
    const int e = blockIdx.z, seg = g_off[e], cnt = g_off[e + 1] - seg;
    const int mtile = blockIdx.y;
    if (mtile * 128 >= cnt) return;
    const int m0g = seg + mtile * 128, n0 = blockIdx.x * 64;

    const int tid = threadIdx.x, warp = tid >> 5, lane = tid & 31;
    const int wm = warp >> 1, wn = warp & 1;
    const uint32_t sb = s2u(smem);

    if (tid == 0) {
        mbar_init(sb + G1_MBAR + 0, 1);
        mbar_init(sb + G1_MBAR + 8, 1);
        mbar_init(sb + G1_MBAR + 16, 1);
    }
    __syncthreads();

    auto issueA = [&](int s) {
        uint32_t mb = sb + G1_MBAR + 8 * (s & 1);
        mbar_expect(mb, 16384);
        tma2d(sb + G1_A + (s & 1) * 16384, &tmA, s * 64, m0g, mb);
    };
    auto issueB = [&](int s) {
        uint32_t mb = sb + G1_MBAR + 16;
        mbar_expect(mb, 32768);
        int k0 = s * 64;
        #pragma unroll
        for (int sub = 0; sub < 2; sub++) {
            tma3d(sb + G1_STG + sub * 8192,          &tmG, n0 + sub * 32, k0, e, mb);
            tma3d(sb + G1_STG + 16384 + sub * 8192,  &tmU, n0 + sub * 32, k0, e, mb);
        }
    };

    if (tid == 0) { issueA(0); issueB(0); }

    float cg[2][4][4] = {}, cu[2][4][4] = {};
    const int KT = DMODEL / 64;
    for (int s = 0; s < KT; s++) {
        const int b1 = s & 1;
        mbar_wait(sb + G1_MBAR + 16, s & 1);
        #pragma unroll
        for (int m = 0; m < 2; m++) {
            char* dst = smem + (m ? G1_B16U : G1_B16G) + b1 * 9216;
            #pragma unroll
            for (int i = 0; i < 4; i++) {
                int id = tid + i * 256;
                int r = id >> 4, c4 = id & 15, sub = c4 >> 3;
                uint32_t so = G1_STG + m * 16384 + sub * 8192
                            + SWZ128((uint32_t)(r * 128 + (c4 & 7) * 16));
                float4 v = *(const float4*)(smem + so);
                sts_f4h(dst, id, v);
            }
        }
        mbar_wait(sb + G1_MBAR + 8 * b1, (s >> 1) & 1);
        __syncthreads();
        if (s + 1 < KT && tid == 0) { issueA(s + 1); issueB(s + 1); }
        uint32_t sA = sb + G1_A + b1 * 16384;
        uint32_t sG = sb + G1_B16G + b1 * 9216;
        uint32_t sU = sb + G1_B16U + b1 * 9216;
        #pragma unroll
        for (int ks = 0; ks < 4; ks++) {
            uint32_t a[2][4], bg[8], bu[8];
            #pragma unroll
            for (int mt = 0; mt < 2; mt++) {
                int row = wm * 32 + mt * 16 + (lane & 15);
                uint32_t off = row * 128 + ks * 32 + (lane >> 4) * 16;
                ldsm4(a[mt], sA + SWZ128(off));
            }
            #pragma unroll
            for (int h = 0; h < 2; h++) {
                int kr = ks * 16 + (lane & 15);
                int nc = wn * 32 + h * 16 + (lane >> 4) * 8;
                ldsm4t(&bg[h * 4], sG + kr * 144 + nc * 2);
                ldsm4t(&bu[h * 4], sU + kr * 144 + nc * 2);
            }
            #pragma unroll
            for (int mt = 0; mt < 2; mt++)
                #pragma unroll
                for (int nt = 0; nt < 4; nt++) {
                    mma16(cg[mt][nt], a[mt], bg[nt * 2], bg[nt * 2 + 1]);
                    mma16(cu[mt][nt], a[mt], bu[nt * 2], bu[nt * 2 + 1]);
                }
        }
    }

    const int quad = lane >> 2, tq = lane & 3;
    const int rowsb = cnt - mtile * 128;
    #pragma unroll
    for (int mt = 0; mt < 2; mt++)
        #pragma unroll
        for (int nt = 0; nt < 4; nt++)
            #pragma unroll
            for (int hr = 0; hr < 2; hr++) {
                int row = wm * 32 + mt * 16 + quad + hr * 8;
                if (row < rowsb) {
                    int c = wn * 32 + nt * 8 + tq * 2;
                    float ga = cg[mt][nt][hr * 2], gb = cg[mt][nt][hr * 2 + 1];
                    float ua = cu[mt][nt][hr * 2], ub = cu[mt][nt][hr * 2 + 1];
                    float ha = ua * (ga / (1.f + __expf(-ga)));
                    float hb = ub * (gb / (1.f + __expf(-gb)));
                    *(__half2*)(g_h + (size_t)(m0g + row) * DFF + n0 + c) =
                        __floats2half2_rn(ha, hb);
                }
            }
}

// ---------------- kernel 4: down GEMM split-K (exact R14) ----------------
__global__ void __launch_bounds__(256, 2)
moe_down_part(const __grid_constant__ CUtensorMap tmA,
              const __grid_constant__ CUtensorMap tmD) {
    extern __shared__ char smem[];
    const int split = blockIdx.z & (NSPLIT - 1), e = blockIdx.z / NSPLIT;
    const int seg = g_off[e], cnt = g_off[e + 1] - seg;
    const int mtile = blockIdx.y;
    if (mtile * 128 >= cnt) return;
    const int m0g = seg + mtile * 128, n0 = blockIdx.x * 64;
    const int kbase = split * (DFF / NSPLIT);

    const int tid = threadIdx.x, warp = tid >> 5, lane = tid & 31;
    const int wm = warp >> 1, wn = warp & 1;
    const uint32_t sb = s2u(smem);

    if (tid == 0) {
        for (int i = 0; i < 3; i++) mbar_init(sb + G2_MBAR + 8 * i, 1);
        mbar_init(sb + G2_MBAR + 24, 1);
        mbar_init(sb + G2_MBAR + 32, 1);
    }
    __syncthreads();

    auto issueA = [&](int s) {
        uint32_t mb = sb + G2_MBAR + 8 * (s % 3);
        mbar_expect(mb, 16384);
        tma2d(sb + G2_A + (s % 3) * 16384, &tmA, kbase + s * 64, m0g, mb);
    };
    auto issueB = [&](int s) {
        uint32_t mb = sb + G2_MBAR + 24 + 8 * (s & 1);
        mbar_expect(mb, 16384);
        int k0 = kbase + s * 64;
        #pragma unroll
        for (int sub = 0; sub < 2; sub++)
            tma3d(sb + G2_STG + (s & 1) * 16384 + sub * 8192, &tmD,
                  n0 + sub * 32, k0, e, mb);
    };

    if (tid == 0) { issueA(0); issueA(1); issueB(0); issueB(1); }

    float acc[2][4][4] = {};
    const int KT = (DFF / NSPLIT) / 64;            // 16 stages
    for (int s = 0; s < KT; s++) {
        const int b1 = s & 1, slotA = s % 3;
        mbar_wait(sb + G2_MBAR + 24 + 8 * b1, (s >> 1) & 1);
        char* dst = smem + G2_B16 + b1 * 9216;
        #pragma unroll
        for (int i = 0; i < 4; i++) {
            int id = tid + i * 256;
            int r = id >> 4, c4 = id & 15, sub = c4 >> 3;
            uint32_t so = G2_STG + b1 * 16384 + sub * 8192
                        + SWZ128((uint32_t)(r * 128 + (c4 & 7) * 16));
            float4 v = *(const float4*)(smem + so);
            sts_f4h(dst, id, v);
        }
        mbar_wait(sb + G2_MBAR + 8 * slotA, (s / 3) & 1);
        __syncthreads();
        if (s + 2 < KT && tid == 0) { issueB(s + 2); issueA(s + 2); }
        uint32_t sA = sb + G2_A + slotA * 16384;
        uint32_t sB = sb + G2_B16 + b1 * 9216;
        #pragma unroll
        for (int ks = 0; ks < 4; ks++) {
            uint32_t a[2][4], bb[8];
            #pragma unroll
            for (int mt = 0; mt < 2; mt++) {
                int row = wm * 32 + mt * 16 + (lane & 15);
                uint32_t off = row * 128 + ks * 32 + (lane >> 4) * 16;
                ldsm4(a[mt], sA + SWZ128(off));
            }
            #pragma unroll
            for (int h = 0; h < 2; h++) {
                int kr = ks * 16 + (lane & 15);
                int nc = wn * 32 + h * 16 + (lane >> 4) * 8;
                ldsm4t(&bb[h * 4], sB + kr * 144 + nc * 2);
            }
            #pragma unroll
            for (int mt = 0; mt < 2; mt++)
                #pragma unroll
                for (int nt = 0; nt < 4; nt++)
                    mma16(acc[mt][nt], a[mt], bb[nt * 2], bb[nt * 2 + 1]);
        }
    }

    const int quad = lane >> 2, tq = lane & 3;
    const int rowsb = cnt - mtile * 128;
    #pragma unroll
    for (int mt = 0; mt < 2; mt++)
        #pragma unroll
        for (int nt = 0; nt < 4; nt++)
            #pragma unroll
            for (int hr = 0; hr < 2; hr++) {
                int row = wm * 32 + mt * 16 + quad + hr * 8;
                if (row < rowsb) {
                    int c = wn * 32 + nt * 8 + tq * 2;
                    float2 v = make_float2(acc[mt][nt][hr * 2], acc[mt][nt][hr * 2 + 1]);
                    *(float2*)(&g_part[split][m0g + row][n0 + c]) = v;
                }
            }
}

// ---------------- kernel 5: reduce partials + scatter ----------------
__global__ void moe_reduce(float* __restrict__ out) {
    int t = blockIdx.x, d = threadIdx.x * 4;
    float4 a = *(const float4*)(&g_part[0][t][d]);
    float4 b = *(const float4*)(&g_part[1][t][d]);
    float4 c = *(const float4*)(&g_part[2][t][d]);
    float4 e = *(const float4*)(&g_part[3][t][d]);
    float4 r;
    r.x = (a.x + b.x) + (c.x + e.x);
    r.y = (a.y + b.y) + (c.y + e.y);
    r.z = (a.z + b.z) + (c.z + e.z);
    r.w = (a.w + b.w) + (c.w + e.w);
    *(float4*)(out + (size_t)g_perm[t] * DMODEL + d) = r;
}

// ---------------- host ----------------
typedef CUresult (*EncFn)(CUtensorMap*, CUtensorMapDataType, cuuint32_t, void*,
    const cuuint64_t*, const cuuint64_t*, const cuuint32_t*, const cuuint32_t*,
    CUtensorMapInterleave, CUtensorMapSwizzle, CUtensorMapL2promotion, CUtensorMapFloatOOBfill);

static void enc_half2d(EncFn f, CUtensorMap* m, void* p, uint64_t d0, uint64_t d1) {
    cuuint64_t dims[2] = {d0, d1}, str[1] = {d0 * 2ULL};
    cuuint32_t box[2] = {64, 128}, es[2] = {1, 1};
    f(m, CU_TENSOR_MAP_DATA_TYPE_UINT16, 2, p, dims, str, box, es,
      CU_TENSOR_MAP_INTERLEAVE_NONE, CU_TENSOR_MAP_SWIZZLE_128B,
      CU_TENSOR_MAP_L2_PROMOTION_L2_128B, CU_TENSOR_MAP_FLOAT_OOB_FILL_NONE);
}
static void enc_w32(EncFn f, CUtensorMap* m, void* p, uint64_t n_dim, uint64_t k_dim) {
    cuuint64_t dims[3] = {n_dim, k_dim, NE};
    cuuint64_t str[2] = {n_dim * 4ULL, n_dim * k_dim * 4ULL};
    cuuint32_t box[3] = {32, 64, 1}, es[3] = {1, 1, 1};
    f(m, CU_TENSOR_MAP_DATA_TYPE_FLOAT32, 3, p, dims, str, box, es,
      CU_TENSOR_MAP_INTERLEAVE_NONE, CU_TENSOR_MAP_SWIZZLE_128B,
      CU_TENSOR_MAP_L2_PROMOTION_L2_128B, CU_TENSOR_MAP_FLOAT_OOB_FILL_NONE);
}

extern "C" void kernel_launch(void* const* d_in, const int* in_sizes, int n_in,
                              void* d_out, int out_size) {
    const float* x  = (const float*)d_in[0];
    const void*  ei = d_in[1];
    void* wg = (void*)d_in[2];
    void* wu = (void*)d_in[3];
    void* wd = (void*)d_in[4];
    float* out = (float*)d_out;

    EncFn enc = nullptr;
    cudaDriverEntryPointQueryResult qr;
    cudaGetDriverEntryPoint("cuTensorMapEncodeTiled", (void**)&enc, cudaEnableDefault, &qr);

    void *p_x16 = nullptr, *p_h = nullptr;
    cudaGetSymbolAddress(&p_x16, g_x16);
    cudaGetSymbolAddress(&p_h, g_h);

    CUtensorMap mA1, mA2, mG, mU, mD;
    enc_half2d(enc, &mA1, p_x16, DMODEL, TTOK);
    enc_half2d(enc, &mA2, p_h, DFF, TTOK);
    enc_w32(enc, &mG, wg, DFF, DMODEL);
    enc_w32(enc, &mU, wu, DFF, DMODEL);
    enc_w32(enc, &mD, wd, DMODEL, DFF);

    cudaFuncSetAttribute(moe_gateup, cudaFuncAttributeMaxDynamicSharedMemorySize, G1_SMEM);
    cudaFuncSetAttribute(moe_down_part, cudaFuncAttributeMaxDynamicSharedMemorySize, G2_SMEM);

    moe_build_perm<<<1, 1024>>>(ei);
    moe_gather<<<TTOK, 256>>>(x);
    moe_gateup<<<dim3(DFF / 64, TTOK / 128, NE), 256, G1_SMEM>>>(mA1, mG, mU);
    moe_down_part<<<dim3(DMODEL / 64, TTOK / 128, NE * NSPLIT), 256, G2_SMEM>>>(mA2, mD);
    moe_reduce<<<TTOK, 256>>>(out);
}